// round 1
// baseline (speedup 1.0000x reference)
#include <cuda_runtime.h>
#include <math.h>
#include <stdint.h>

#define SEQ   4096
#define BATCH 32
#define HID   512
#define TOK   (SEQ*BATCH)

#define MT 128
#define NT 64
#define KT 32
#define ASTRIDE (KT + 4)   // 36 words: 36 % 32 == 4 -> bank = 4*row + k, conflict-free frags

__device__ float g_sim[TOK];
__device__ float g_probs[TOK];

__device__ __forceinline__ uint32_t f2tf32(float f) {
    uint32_t r;
    asm("cvt.rna.tf32.f32 %0, %1;" : "=r"(r) : "f"(f));
    return r;
}

// ---------------------------------------------------------------------------
// Kernel 0: zero sim scratch and the (poisoned) output buffer
// ---------------------------------------------------------------------------
__global__ void init_kernel(float* __restrict__ out) {
    int i = blockIdx.x * blockDim.x + threadIdx.x;   // grid covers exactly TOK
    g_sim[i] = 0.f;
    if (i < BATCH * HID) out[i] = 0.f;
}

// ---------------------------------------------------------------------------
// Kernel 1: z = X @ W^T (tf32 mma), fused tanh(z+b)·ctx reduction -> g_sim
// X viewed as [TOK, HID] row-major (token t = s*BATCH + b is contiguous).
// Grid: (TOK/MT, HID/NT). 256 threads = 8 warps in 4(m) x 2(n) layout.
// ---------------------------------------------------------------------------
__global__ __launch_bounds__(256, 2)
void sim_kernel(const float* __restrict__ X, const float* __restrict__ W,
                const float* __restrict__ bias, const float* __restrict__ ctx)
{
    __shared__ uint32_t As[MT * ASTRIDE];
    __shared__ uint32_t Bs[NT * ASTRIDE];

    const int tid  = threadIdx.x;
    const int m0   = blockIdx.x * MT;
    const int n0   = blockIdx.y * NT;
    const int warp = tid >> 5;
    const int lane = tid & 31;
    const int g    = lane >> 2;       // group id (row within mma tile)
    const int l4   = lane & 3;        // thread-in-group
    const int wm   = warp & 3;        // 0..3 -> 32 rows each
    const int wn   = warp >> 2;       // 0..1 -> 32 cols each

    float acc[2][4][4];
    #pragma unroll
    for (int i = 0; i < 2; i++)
        #pragma unroll
        for (int j = 0; j < 4; j++)
            #pragma unroll
            for (int c = 0; c < 4; c++) acc[i][j][c] = 0.f;

    for (int kt = 0; kt < HID; kt += KT) {
        // ---- stage A tile: 128 x 32 (1024 float4) ----
        #pragma unroll
        for (int i = 0; i < 4; i++) {
            int idx = tid + i * 256;
            int row = idx >> 3;
            int c4  = (idx & 7) << 2;
            const float4 v = *reinterpret_cast<const float4*>(
                &X[(size_t)(m0 + row) * HID + kt + c4]);
            uint32_t* dst = &As[row * ASTRIDE + c4];
            dst[0] = f2tf32(v.x); dst[1] = f2tf32(v.y);
            dst[2] = f2tf32(v.z); dst[3] = f2tf32(v.w);
        }
        // ---- stage B tile: 64 x 32 (512 float4); B[k][n] = W[n][k] ----
        #pragma unroll
        for (int i = 0; i < 2; i++) {
            int idx = tid + i * 256;
            int row = idx >> 3;
            int c4  = (idx & 7) << 2;
            const float4 v = *reinterpret_cast<const float4*>(
                &W[(size_t)(n0 + row) * HID + kt + c4]);
            uint32_t* dst = &Bs[row * ASTRIDE + c4];
            dst[0] = f2tf32(v.x); dst[1] = f2tf32(v.y);
            dst[2] = f2tf32(v.z); dst[3] = f2tf32(v.w);
        }
        __syncthreads();

        #pragma unroll
        for (int kk = 0; kk < KT; kk += 8) {
            uint32_t a[2][4], bf[4][2];
            #pragma unroll
            for (int mi = 0; mi < 2; mi++) {
                int r = wm * 32 + mi * 16;
                a[mi][0] = As[(r + g    ) * ASTRIDE + kk + l4    ];
                a[mi][1] = As[(r + g + 8) * ASTRIDE + kk + l4    ];
                a[mi][2] = As[(r + g    ) * ASTRIDE + kk + l4 + 4];
                a[mi][3] = As[(r + g + 8) * ASTRIDE + kk + l4 + 4];
            }
            #pragma unroll
            for (int ni = 0; ni < 4; ni++) {
                int c = wn * 32 + ni * 8 + g;
                bf[ni][0] = Bs[c * ASTRIDE + kk + l4    ];
                bf[ni][1] = Bs[c * ASTRIDE + kk + l4 + 4];
            }
            #pragma unroll
            for (int mi = 0; mi < 2; mi++)
                #pragma unroll
                for (int ni = 0; ni < 4; ni++)
                    asm volatile(
                        "mma.sync.aligned.m16n8k8.row.col.f32.tf32.tf32.f32 "
                        "{%0,%1,%2,%3}, {%4,%5,%6,%7}, {%8,%9}, {%0,%1,%2,%3};"
                        : "+f"(acc[mi][ni][0]), "+f"(acc[mi][ni][1]),
                          "+f"(acc[mi][ni][2]), "+f"(acc[mi][ni][3])
                        : "r"(a[mi][0]), "r"(a[mi][1]), "r"(a[mi][2]), "r"(a[mi][3]),
                          "r"(bf[ni][0]), "r"(bf[ni][1]));
        }
        __syncthreads();
    }

    // ---- epilogue: sim partial = sum over this block's 64 cols of tanh(z+b)*ctx ----
    // c0,c1 -> row g, cols 2*l4, 2*l4+1 ; c2,c3 -> row g+8
    float rowsum[2][2] = {{0.f, 0.f}, {0.f, 0.f}};
    #pragma unroll
    for (int ni = 0; ni < 4; ni++) {
        int col = n0 + wn * 32 + ni * 8 + 2 * l4;
        float b0 = bias[col], b1 = bias[col + 1];
        float c0 = ctx[col],  c1 = ctx[col + 1];
        #pragma unroll
        for (int mi = 0; mi < 2; mi++) {
            rowsum[mi][0] += tanhf(acc[mi][ni][0] + b0) * c0
                           + tanhf(acc[mi][ni][1] + b1) * c1;
            rowsum[mi][1] += tanhf(acc[mi][ni][2] + b0) * c0
                           + tanhf(acc[mi][ni][3] + b1) * c1;
        }
    }
    #pragma unroll
    for (int mi = 0; mi < 2; mi++)
        #pragma unroll
        for (int hf = 0; hf < 2; hf++) {
            float v = rowsum[mi][hf];
            v += __shfl_xor_sync(0xffffffffu, v, 1);
            v += __shfl_xor_sync(0xffffffffu, v, 2);
            if (l4 == 0)
                atomicAdd(&g_sim[m0 + wm * 32 + mi * 16 + g + hf * 8], v);
        }
}

// ---------------------------------------------------------------------------
// Kernel 2: softmax over seq for each batch. sim index t = s*BATCH + b.
// One block per batch element.
// ---------------------------------------------------------------------------
__global__ void softmax_kernel()
{
    const int b   = blockIdx.x;
    const int tid = threadIdx.x;
    __shared__ float red[256];

    float lmax = -1e30f;
    for (int s = tid; s < SEQ; s += 256)
        lmax = fmaxf(lmax, g_sim[s * BATCH + b]);
    red[tid] = lmax; __syncthreads();
    for (int o = 128; o > 0; o >>= 1) {
        if (tid < o) red[tid] = fmaxf(red[tid], red[tid + o]);
        __syncthreads();
    }
    const float m = red[0];
    __syncthreads();

    float lsum = 0.f;
    for (int s = tid; s < SEQ; s += 256)
        lsum += __expf(g_sim[s * BATCH + b] - m);
    red[tid] = lsum; __syncthreads();
    for (int o = 128; o > 0; o >>= 1) {
        if (tid < o) red[tid] += red[tid + o];
        __syncthreads();
    }
    const float inv = 1.f / red[0];

    for (int s = tid; s < SEQ; s += 256)
        g_probs[s * BATCH + b] = __expf(g_sim[s * BATCH + b] - m) * inv;
}

// ---------------------------------------------------------------------------
// Kernel 3: attended[b,h] = sum_s x[s,b,h] * p[b,s]. s-split with atomics.
// Grid: (BATCH, HID/128, 16 s-chunks), 128 threads.
// ---------------------------------------------------------------------------
__global__ __launch_bounds__(128)
void pool_kernel(const float* __restrict__ X, float* __restrict__ out)
{
    const int b  = blockIdx.x;
    const int h  = blockIdx.y * 128 + threadIdx.x;
    const int s0 = blockIdx.z * (SEQ / 16);

    float acc = 0.f;
    #pragma unroll 4
    for (int s = s0; s < s0 + SEQ / 16; s++) {
        const int t = s * BATCH + b;
        acc += X[(size_t)t * HID + h] * g_probs[t];
    }
    atomicAdd(&out[b * HID + h], acc);
}

// ---------------------------------------------------------------------------
extern "C" void kernel_launch(void* const* d_in, const int* in_sizes, int n_in,
                              void* d_out, int out_size)
{
    const float* x   = (const float*)d_in[0];
    const float* W   = (const float*)d_in[1];
    const float* b   = (const float*)d_in[2];
    const float* ctx = (const float*)d_in[3];
    float* out = (float*)d_out;

    init_kernel<<<TOK / 256, 256>>>(out);

    dim3 grid_sim(TOK / MT, HID / NT);
    sim_kernel<<<grid_sim, 256>>>(x, W, b, ctx);

    softmax_kernel<<<BATCH, 256>>>();

    pool_kernel<<<dim3(BATCH, HID / 128, 16), 128>>>(x, out);
}

// round 3
// speedup vs baseline: 1.4630x; 1.4630x over previous
#include <cuda_runtime.h>
#include <math.h>
#include <stdint.h>

#define SEQ   4096
#define BATCH 32
#define HID   512
#define TOK   (SEQ*BATCH)

#define MT 128
#define NT 128
#define KT 32
#define ASTRIDE (KT + 4)            // 36 words; 144B row stride (16B aligned for cp.async)
#define STAGE   ((MT + NT) * ASTRIDE)   // words per pipeline stage
#define SMEM_BYTES (2 * STAGE * 4)

__device__ float g_sim[TOK];
__device__ float g_probs[TOK];

// ---------------------------------------------------------------------------
// Kernel 0: zero sim scratch and the (poisoned) output buffer
// ---------------------------------------------------------------------------
__global__ void init_kernel(float* __restrict__ out) {
    int i = blockIdx.x * blockDim.x + threadIdx.x;   // grid covers exactly TOK
    g_sim[i] = 0.f;
    if (i < BATCH * HID) out[i] = 0.f;
}

__device__ __forceinline__ void cp16(uint32_t* smem_dst, const float* gsrc) {
    uint32_t s = (uint32_t)__cvta_generic_to_shared(smem_dst);
    asm volatile("cp.async.cg.shared.global [%0], [%1], 16;\n" :: "r"(s), "l"(gsrc));
}

// ---------------------------------------------------------------------------
// Kernel 1: z = X @ W^T (tf32 mma, fp32 bits fed directly — HW truncation),
// fused tanh(z+b)*ctx reduction -> g_sim.
// X viewed as [TOK, HID] row-major (token t = s*BATCH + b contiguous).
// Grid: (HID/NT, TOK/MT)  -- n-tile fastest so same-m CTAs share X via L2.
// 256 threads = 8 warps, 2(m) x 4(n); each warp owns 64x32 of the 128x128 tile.
// ---------------------------------------------------------------------------
__global__ __launch_bounds__(256, 2)
void sim_kernel(const float* __restrict__ X, const float* __restrict__ W,
                const float* __restrict__ bias, const float* __restrict__ ctx)
{
    extern __shared__ uint32_t smem[];

    const int tid  = threadIdx.x;
    const int n0   = blockIdx.x * NT;
    const int m0   = blockIdx.y * MT;
    const int warp = tid >> 5;
    const int lane = tid & 31;
    const int g    = lane >> 2;
    const int l4   = lane & 3;
    const int wm   = warp & 1;        // 0..1 -> 64 rows each
    const int wn   = warp >> 1;       // 0..3 -> 32 cols each

    float acc[4][4][4];
    #pragma unroll
    for (int i = 0; i < 4; i++)
        #pragma unroll
        for (int j = 0; j < 4; j++)
            #pragma unroll
            for (int c = 0; c < 4; c++) acc[i][j][c] = 0.f;

    const int NK = HID / KT;   // 16

    // stage a k-tile (A: 128x32, B: 128x32) via cp.async
    auto load_tile = [&](int kt_idx, int stage) {
        uint32_t* As = smem + stage * STAGE;
        uint32_t* Bs = As + MT * ASTRIDE;
        const int kt = kt_idx * KT;
        #pragma unroll
        for (int i = 0; i < 4; i++) {             // 1024 float4 for A (128 rows x 8)
            int idx = tid + i * 256;
            int row = idx >> 3;
            int c4  = (idx & 7) << 2;
            cp16(&As[row * ASTRIDE + c4], &X[(size_t)(m0 + row) * HID + kt + c4]);
        }
        #pragma unroll
        for (int i = 0; i < 4; i++) {             // 1024 float4 for B (128 rows x 8)
            int idx = tid + i * 256;
            int row = idx >> 3;
            int c4  = (idx & 7) << 2;
            cp16(&Bs[row * ASTRIDE + c4], &W[(size_t)(n0 + row) * HID + kt + c4]);
        }
        asm volatile("cp.async.commit_group;\n");
    };

    load_tile(0, 0);

    for (int i = 0; i < NK; i++) {
        if (i + 1 < NK) {
            load_tile(i + 1, (i + 1) & 1);
            asm volatile("cp.async.wait_group 1;\n");
        } else {
            asm volatile("cp.async.wait_group 0;\n");
        }
        __syncthreads();

        const uint32_t* As = smem + (i & 1) * STAGE;
        const uint32_t* Bs = As + MT * ASTRIDE;

        #pragma unroll
        for (int kk = 0; kk < KT; kk += 8) {
            uint32_t a[4][4], bf[4][2];
            #pragma unroll
            for (int mi = 0; mi < 4; mi++) {
                int r = wm * 64 + mi * 16;
                a[mi][0] = As[(r + g    ) * ASTRIDE + kk + l4    ];
                a[mi][1] = As[(r + g + 8) * ASTRIDE + kk + l4    ];
                a[mi][2] = As[(r + g    ) * ASTRIDE + kk + l4 + 4];
                a[mi][3] = As[(r + g + 8) * ASTRIDE + kk + l4 + 4];
            }
            #pragma unroll
            for (int ni = 0; ni < 4; ni++) {
                int c = wn * 32 + ni * 8 + g;
                bf[ni][0] = Bs[c * ASTRIDE + kk + l4    ];
                bf[ni][1] = Bs[c * ASTRIDE + kk + l4 + 4];
            }
            #pragma unroll
            for (int mi = 0; mi < 4; mi++)
                #pragma unroll
                for (int ni = 0; ni < 4; ni++)
                    asm volatile(
                        "mma.sync.aligned.m16n8k8.row.col.f32.tf32.tf32.f32 "
                        "{%0,%1,%2,%3}, {%4,%5,%6,%7}, {%8,%9}, {%0,%1,%2,%3};"
                        : "+f"(acc[mi][ni][0]), "+f"(acc[mi][ni][1]),
                          "+f"(acc[mi][ni][2]), "+f"(acc[mi][ni][3])
                        : "r"(a[mi][0]), "r"(a[mi][1]), "r"(a[mi][2]), "r"(a[mi][3]),
                          "r"(bf[ni][0]), "r"(bf[ni][1]));
        }
        __syncthreads();
    }

    // ---- epilogue: partial sim = sum over this block's 128 cols of tanh(z+b)*ctx ----
    float rowsum[4][2];
    #pragma unroll
    for (int mi = 0; mi < 4; mi++) { rowsum[mi][0] = 0.f; rowsum[mi][1] = 0.f; }

    #pragma unroll
    for (int ni = 0; ni < 4; ni++) {
        int col = n0 + wn * 32 + ni * 8 + 2 * l4;
        float b0 = bias[col], b1 = bias[col + 1];
        float c0 = ctx[col],  c1 = ctx[col + 1];
        #pragma unroll
        for (int mi = 0; mi < 4; mi++) {
            rowsum[mi][0] += tanhf(acc[mi][ni][0] + b0) * c0
                           + tanhf(acc[mi][ni][1] + b1) * c1;
            rowsum[mi][1] += tanhf(acc[mi][ni][2] + b0) * c0
                           + tanhf(acc[mi][ni][3] + b1) * c1;
        }
    }
    #pragma unroll
    for (int mi = 0; mi < 4; mi++)
        #pragma unroll
        for (int hf = 0; hf < 2; hf++) {
            float v = rowsum[mi][hf];
            v += __shfl_xor_sync(0xffffffffu, v, 1);
            v += __shfl_xor_sync(0xffffffffu, v, 2);
            if (l4 == 0)
                atomicAdd(&g_sim[m0 + wm * 64 + mi * 16 + g + hf * 8], v);
        }
}

// ---------------------------------------------------------------------------
// Kernel 2: softmax over seq for each batch. sim index t = s*BATCH + b.
// ---------------------------------------------------------------------------
__global__ void softmax_kernel()
{
    const int b   = blockIdx.x;
    const int tid = threadIdx.x;
    __shared__ float red[256];

    float lmax = -1e30f;
    for (int s = tid; s < SEQ; s += 256)
        lmax = fmaxf(lmax, g_sim[s * BATCH + b]);
    red[tid] = lmax; __syncthreads();
    for (int o = 128; o > 0; o >>= 1) {
        if (tid < o) red[tid] = fmaxf(red[tid], red[tid + o]);
        __syncthreads();
    }
    const float m = red[0];
    __syncthreads();

    float lsum = 0.f;
    for (int s = tid; s < SEQ; s += 256) {
        float e = __expf(g_sim[s * BATCH + b] - m);
        g_probs[s * BATCH + b] = e;          // stash exp
        lsum += e;
    }
    red[tid] = lsum; __syncthreads();
    for (int o = 128; o > 0; o >>= 1) {
        if (tid < o) red[tid] += red[tid + o];
        __syncthreads();
    }
    const float inv = 1.f / red[0];

    for (int s = tid; s < SEQ; s += 256)
        g_probs[s * BATCH + b] *= inv;
}

// ---------------------------------------------------------------------------
// Kernel 3: attended[b,h] = sum_s x[s,b,h] * p[b,s]. float4, s-split atomics.
// Grid: (BATCH, 1, 16 s-chunks), 128 threads (128*4 = 512 = HID floats).
// ---------------------------------------------------------------------------
__global__ __launch_bounds__(128)
void pool_kernel(const float* __restrict__ X, float* __restrict__ out)
{
    const int b  = blockIdx.x;
    const int h4 = threadIdx.x;               // float4 index into the hid dim
    const int s0 = blockIdx.z * (SEQ / 16);

    float4 acc = make_float4(0.f, 0.f, 0.f, 0.f);
    const float4* X4 = reinterpret_cast<const float4*>(X);

    #pragma unroll 4
    for (int s = s0; s < s0 + SEQ / 16; s++) {
        const int t = s * BATCH + b;
        const float p = g_probs[t];
        const float4 v = X4[(size_t)t * (HID / 4) + h4];
        acc.x += v.x * p; acc.y += v.y * p; acc.z += v.z * p; acc.w += v.w * p;
    }
    float* o = &out[b * HID + h4 * 4];
    atomicAdd(o + 0, acc.x);
    atomicAdd(o + 1, acc.y);
    atomicAdd(o + 2, acc.z);
    atomicAdd(o + 3, acc.w);
}

// ---------------------------------------------------------------------------
extern "C" void kernel_launch(void* const* d_in, const int* in_sizes, int n_in,
                              void* d_out, int out_size)
{
    const float* x   = (const float*)d_in[0];
    const float* W   = (const float*)d_in[1];
    const float* b   = (const float*)d_in[2];
    const float* ctx = (const float*)d_in[3];
    float* out = (float*)d_out;

    cudaFuncSetAttribute(sim_kernel,
                         cudaFuncAttributeMaxDynamicSharedMemorySize, SMEM_BYTES);

    init_kernel<<<TOK / 256, 256>>>(out);

    dim3 grid_sim(HID / NT, TOK / MT);        // n fastest -> X reuse in L2
    sim_kernel<<<grid_sim, 256, SMEM_BYTES>>>(x, W, b, ctx);

    softmax_kernel<<<BATCH, 256>>>();

    pool_kernel<<<dim3(BATCH, 1, 16), 128>>>(x, out);
}

// round 5
// speedup vs baseline: 1.5256x; 1.0428x over previous
#include <cuda_runtime.h>
#include <math.h>
#include <stdint.h>

#define SEQ   4096
#define BATCH 32
#define HID   512
#define TOK   (SEQ*BATCH)

#define MT 256
#define NT 128
#define KT 32
#define NSTAGE 4
#define ASTRIDE (KT + 4)                    // 36 words; 144B row stride (16B aligned)
#define STAGE   ((MT + NT) * ASTRIDE)       // words per stage (13824 = 55296 B)
#define SMEM_BYTES (NSTAGE * STAGE * 4)     // 221184 B <= 227 KB

__device__ float g_sim[TOK];
__device__ float g_probs[TOK];

// ---------------------------------------------------------------------------
// Kernel 0: zero sim scratch and the (poisoned) output buffer
// ---------------------------------------------------------------------------
__global__ void init_kernel(float* __restrict__ out) {
    int i = blockIdx.x * blockDim.x + threadIdx.x;   // grid covers exactly TOK
    g_sim[i] = 0.f;
    if (i < BATCH * HID) out[i] = 0.f;
}

__device__ __forceinline__ void cp16(uint32_t* smem_dst, const float* gsrc) {
    uint32_t s = (uint32_t)__cvta_generic_to_shared(smem_dst);
    asm volatile("cp.async.cg.shared.global [%0], [%1], 16;\n" :: "r"(s), "l"(gsrc));
}

// ---------------------------------------------------------------------------
// Kernel 1: z = X @ W^T (tf32 mma.sync, fp32 bits fed raw — HW truncation),
// fused tanh(z+b)*ctx reduction -> g_sim.
// X viewed as [TOK, HID] row-major (token t = s*BATCH + b contiguous).
// Grid: (HID/NT=4, TOK/MT=512), n fastest -> X L2 reuse across the 4 n-CTAs.
// 512 threads = 16 warps in 4(m) x 4(n); warp tile 64x32 (mi=4, ni=4).
// 4-stage cp.async ring, depth-2 prefetch, single __syncthreads per k-tile.
// ---------------------------------------------------------------------------
__global__ __launch_bounds__(512, 1)
void sim_kernel(const float* __restrict__ X, const float* __restrict__ W,
                const float* __restrict__ bias, const float* __restrict__ ctx)
{
    extern __shared__ uint32_t smem[];

    const int tid  = threadIdx.x;
    const int n0   = blockIdx.x * NT;
    const int m0   = blockIdx.y * MT;
    const int warp = tid >> 5;
    const int lane = tid & 31;
    const int g    = lane >> 2;
    const int l4   = lane & 3;
    const int wm   = warp & 3;        // 0..3 -> 64 rows each
    const int wn   = warp >> 2;       // 0..3 -> 32 cols each

    float acc[4][4][4];
    #pragma unroll
    for (int i = 0; i < 4; i++)
        #pragma unroll
        for (int j = 0; j < 4; j++)
            #pragma unroll
            for (int c = 0; c < 4; c++) acc[i][j][c] = 0.f;

    const int NK = HID / KT;   // 16 k-tiles

    // stage a k-tile (A: 256x32, B: 128x32) via cp.async: 3072 x 16B, 6/thread
    auto load_tile = [&](int kt_idx, int s) {
        uint32_t* As = smem + s * STAGE;
        uint32_t* Bs = As + MT * ASTRIDE;
        const int kt = kt_idx * KT;
        #pragma unroll
        for (int i = 0; i < 4; i++) {             // 2048 chunks for A (256 rows x 8)
            int idx = tid + i * 512;
            int row = idx >> 3;
            int c4  = (idx & 7) << 2;
            cp16(&As[row * ASTRIDE + c4], &X[(size_t)(m0 + row) * HID + kt + c4]);
        }
        #pragma unroll
        for (int i = 0; i < 2; i++) {             // 1024 chunks for B (128 rows x 8)
            int idx = tid + i * 512;
            int row = idx >> 3;
            int c4  = (idx & 7) << 2;
            cp16(&Bs[row * ASTRIDE + c4], &W[(size_t)(n0 + row) * HID + kt + c4]);
        }
        asm volatile("cp.async.commit_group;\n");
    };

    // depth-2 prefetch into 4-stage ring
    load_tile(0, 0);
    load_tile(1, 1);

    for (int i = 0; i < NK; i++) {
        if (i + 2 < NK) load_tile(i + 2, (i + 2) & 3);

        if (i < NK - 2)      asm volatile("cp.async.wait_group 2;\n" ::: "memory");
        else if (i == NK - 2) asm volatile("cp.async.wait_group 1;\n" ::: "memory");
        else                 asm volatile("cp.async.wait_group 0;\n" ::: "memory");
        __syncthreads();     // single barrier per k-tile (safe: overwritten stage
                             // was last read at iter i-2; barrier i-1 cleared it)

        const uint32_t* As = smem + (i & 3) * STAGE;
        const uint32_t* Bs = As + MT * ASTRIDE;

        #pragma unroll
        for (int kk = 0; kk < KT; kk += 8) {
            uint32_t a[4][4], bf[4][2];
            #pragma unroll
            for (int mi = 0; mi < 4; mi++) {
                int r = wm * 64 + mi * 16;
                a[mi][0] = As[(r + g    ) * ASTRIDE + kk + l4    ];
                a[mi][1] = As[(r + g + 8) * ASTRIDE + kk + l4    ];
                a[mi][2] = As[(r + g    ) * ASTRIDE + kk + l4 + 4];
                a[mi][3] = As[(r + g + 8) * ASTRIDE + kk + l4 + 4];
            }
            #pragma unroll
            for (int ni = 0; ni < 4; ni++) {
                int c = wn * 32 + ni * 8 + g;
                bf[ni][0] = Bs[c * ASTRIDE + kk + l4    ];
                bf[ni][1] = Bs[c * ASTRIDE + kk + l4 + 4];
            }
            #pragma unroll
            for (int mi = 0; mi < 4; mi++)
                #pragma unroll
                for (int ni = 0; ni < 4; ni++)
                    asm volatile(
                        "mma.sync.aligned.m16n8k8.row.col.f32.tf32.tf32.f32 "
                        "{%0,%1,%2,%3}, {%4,%5,%6,%7}, {%8,%9}, {%0,%1,%2,%3};"
                        : "+f"(acc[mi][ni][0]), "+f"(acc[mi][ni][1]),
                          "+f"(acc[mi][ni][2]), "+f"(acc[mi][ni][3])
                        : "r"(a[mi][0]), "r"(a[mi][1]), "r"(a[mi][2]), "r"(a[mi][3]),
                          "r"(bf[ni][0]), "r"(bf[ni][1]));
        }
    }

    // ---- epilogue: partial sim = sum over this block's 128 cols of tanh(z+b)*ctx ----
    float rowsum[4][2];
    #pragma unroll
    for (int mi = 0; mi < 4; mi++) { rowsum[mi][0] = 0.f; rowsum[mi][1] = 0.f; }

    #pragma unroll
    for (int ni = 0; ni < 4; ni++) {
        int col = n0 + wn * 32 + ni * 8 + 2 * l4;
        float b0 = bias[col], b1 = bias[col + 1];
        float c0 = ctx[col],  c1 = ctx[col + 1];
        #pragma unroll
        for (int mi = 0; mi < 4; mi++) {
            rowsum[mi][0] += tanhf(acc[mi][ni][0] + b0) * c0
                           + tanhf(acc[mi][ni][1] + b1) * c1;
            rowsum[mi][1] += tanhf(acc[mi][ni][2] + b0) * c0
                           + tanhf(acc[mi][ni][3] + b1) * c1;
        }
    }
    #pragma unroll
    for (int mi = 0; mi < 4; mi++)
        #pragma unroll
        for (int hf = 0; hf < 2; hf++) {
            float v = rowsum[mi][hf];
            v += __shfl_xor_sync(0xffffffffu, v, 1);
            v += __shfl_xor_sync(0xffffffffu, v, 2);
            if (l4 == 0)
                atomicAdd(&g_sim[m0 + wm * 64 + mi * 16 + g + hf * 8], v);
        }
}

// ---------------------------------------------------------------------------
// Kernel 2: softmax over seq per batch. sim index t = s*BATCH + b.
// ---------------------------------------------------------------------------
__global__ void softmax_kernel()
{
    const int b   = blockIdx.x;
    const int tid = threadIdx.x;
    __shared__ float red[256];

    float lmax = -1e30f;
    for (int s = tid; s < SEQ; s += 256)
        lmax = fmaxf(lmax, g_sim[s * BATCH + b]);
    red[tid] = lmax; __syncthreads();
    for (int o = 128; o > 0; o >>= 1) {
        if (tid < o) red[tid] = fmaxf(red[tid], red[tid + o]);
        __syncthreads();
    }
    const float m = red[0];
    __syncthreads();

    float lsum = 0.f;
    for (int s = tid; s < SEQ; s += 256) {
        float e = __expf(g_sim[s * BATCH + b] - m);
        g_probs[s * BATCH + b] = e;
        lsum += e;
    }
    red[tid] = lsum; __syncthreads();
    for (int o = 128; o > 0; o >>= 1) {
        if (tid < o) red[tid] += red[tid + o];
        __syncthreads();
    }
    const float inv = 1.f / red[0];

    for (int s = tid; s < SEQ; s += 256)
        g_probs[s * BATCH + b] *= inv;
}

// ---------------------------------------------------------------------------
// Kernel 3: attended[b,h] = sum_s x[s,b,h]*p[b,s]. float4, 64 s-chunks.
// Grid: (BATCH, 1, 64) = 2048 blocks, 128 threads.
// ---------------------------------------------------------------------------
__global__ __launch_bounds__(128)
void pool_kernel(const float* __restrict__ X, float* __restrict__ out)
{
    const int b  = blockIdx.x;
    const int h4 = threadIdx.x;
    const int s0 = blockIdx.z * (SEQ / 64);

    float4 acc = make_float4(0.f, 0.f, 0.f, 0.f);
    const float4* X4 = reinterpret_cast<const float4*>(X);

    #pragma unroll 4
    for (int s = s0; s < s0 + SEQ / 64; s++) {
        const int t = s * BATCH + b;
        const float p = g_probs[t];
        const float4 v = X4[(size_t)t * (HID / 4) + h4];
        acc.x += v.x * p; acc.y += v.y * p; acc.z += v.z * p; acc.w += v.w * p;
    }
    float* o = &out[b * HID + h4 * 4];
    atomicAdd(o + 0, acc.x);
    atomicAdd(o + 1, acc.y);
    atomicAdd(o + 2, acc.z);
    atomicAdd(o + 3, acc.w);
}

// ---------------------------------------------------------------------------
extern "C" void kernel_launch(void* const* d_in, const int* in_sizes, int n_in,
                              void* d_out, int out_size)
{
    const float* x   = (const float*)d_in[0];
    const float* W   = (const float*)d_in[1];
    const float* b   = (const float*)d_in[2];
    const float* ctx = (const float*)d_in[3];
    float* out = (float*)d_out;

    cudaFuncSetAttribute(sim_kernel,
                         cudaFuncAttributeMaxDynamicSharedMemorySize, SMEM_BYTES);

    init_kernel<<<TOK / 256, 256>>>(out);

    dim3 grid_sim(HID / NT, TOK / MT);        // n fastest -> X reuse in L2
    sim_kernel<<<grid_sim, 512, SMEM_BYTES>>>(x, W, b, ctx);

    softmax_kernel<<<BATCH, 256>>>();

    pool_kernel<<<dim3(BATCH, 1, 64), 128>>>(x, out);
}

// round 7
// speedup vs baseline: 2.0709x; 1.3574x over previous
#include <cuda_runtime.h>
#include <cuda_fp16.h>
#include <math.h>
#include <stdint.h>

#define SEQ   4096
#define BATCH 32
#define HID   512
#define TOK   (SEQ*BATCH)

#define MT 256
#define NT 128
#define KT 64                               // 64 halfs = 128 B per row
#define NSTAGE 4
#define ASTRIDE (KT + 8)                    // 72 halfs = 144 B (16B aligned, conflict-free)
#define STAGE   ((MT + NT) * ASTRIDE)       // halfs per stage (27648 = 55296 B)
#define SMEM_BYTES (NSTAGE * STAGE * 2)     // 221184 B

__device__ float  g_sim[TOK];
__device__ float  g_probs[TOK];
__device__ __half g_X16[(size_t)TOK * HID];   // 128 MB static scratch (allowed)
__device__ __half g_W16[HID * HID];

// ---------------------------------------------------------------------------
// Kernel 0: zero sim + output, convert W to fp16.
// ---------------------------------------------------------------------------
__global__ void init_kernel(const float* __restrict__ W, float* __restrict__ out) {
    int i = blockIdx.x * blockDim.x + threadIdx.x;   // grid covers exactly TOK
    g_sim[i] = 0.f;
    if (i < BATCH * HID) out[i] = 0.f;
    if (i < (HID * HID) / 8) {                       // 32768 threads x 8 elems
        const float4* src = reinterpret_cast<const float4*>(W) + i * 2;
        __half2* dst = reinterpret_cast<__half2*>(g_W16) + i * 4;
        float4 v0 = src[0], v1 = src[1];
        dst[0] = __float22half2_rn(make_float2(v0.x, v0.y));
        dst[1] = __float22half2_rn(make_float2(v0.z, v0.w));
        dst[2] = __float22half2_rn(make_float2(v1.x, v1.y));
        dst[3] = __float22half2_rn(make_float2(v1.z, v1.w));
    }
}

// ---------------------------------------------------------------------------
// Kernel 0b: convert X to fp16 (8 elems/thread, vectorized)
// ---------------------------------------------------------------------------
__global__ __launch_bounds__(256)
void convert_kernel(const float* __restrict__ X) {
    size_t i = (size_t)blockIdx.x * blockDim.x + threadIdx.x;   // grid covers TOK*HID/8
    const float4* src = reinterpret_cast<const float4*>(X) + i * 2;
    __half2* dst = reinterpret_cast<__half2*>(g_X16) + i * 4;
    float4 v0 = src[0], v1 = src[1];
    dst[0] = __float22half2_rn(make_float2(v0.x, v0.y));
    dst[1] = __float22half2_rn(make_float2(v0.z, v0.w));
    dst[2] = __float22half2_rn(make_float2(v1.x, v1.y));
    dst[3] = __float22half2_rn(make_float2(v1.z, v1.w));
}

__device__ __forceinline__ void cp16(const __half* smem_dst, const __half* gsrc) {
    uint32_t s = (uint32_t)__cvta_generic_to_shared(smem_dst);
    asm volatile("cp.async.cg.shared.global [%0], [%1], 16;\n" :: "r"(s), "l"(gsrc));
}

// ---------------------------------------------------------------------------
// Kernel 1: z = X @ W^T (fp16 m16n8k16 mma, fp32 acc), fused tanh(z+b)*ctx -> g_sim.
// Grid: (HID/NT=4, TOK/MT=512) n-fastest. 512 thr = 16 warps 4(m)x4(n),
// warp tile 64x32. 4-stage cp.async ring, depth-2, one __syncthreads per k-tile.
// ---------------------------------------------------------------------------
__global__ __launch_bounds__(512, 1)
void sim_kernel(const float* __restrict__ bias, const float* __restrict__ ctx)
{
    extern __shared__ __half smem[];

    const int tid  = threadIdx.x;
    const int n0   = blockIdx.x * NT;
    const int m0   = blockIdx.y * MT;
    const int warp = tid >> 5;
    const int lane = tid & 31;
    const int g    = lane >> 2;
    const int l4   = lane & 3;
    const int wm   = warp & 3;        // 0..3 -> 64 rows each
    const int wn   = warp >> 2;       // 0..3 -> 32 cols each

    float acc[4][4][4];
    #pragma unroll
    for (int i = 0; i < 4; i++)
        #pragma unroll
        for (int j = 0; j < 4; j++)
            #pragma unroll
            for (int c = 0; c < 4; c++) acc[i][j][c] = 0.f;

    const int NK = HID / KT;   // 8 k-tiles

    // stage a k-tile (A: 256x64h, B: 128x64h) = 3072 x 16B chunks, 6/thread
    auto load_tile = [&](int kt_idx, int s) {
        __half* As = smem + s * STAGE;
        __half* Bs = As + MT * ASTRIDE;
        const int kt = kt_idx * KT;
        #pragma unroll
        for (int i = 0; i < 4; i++) {             // 2048 chunks for A (256 rows x 8)
            int idx = tid + i * 512;
            int row = idx >> 3;
            int c8  = (idx & 7) << 3;             // half offset within row
            cp16(&As[row * ASTRIDE + c8], &g_X16[(size_t)(m0 + row) * HID + kt + c8]);
        }
        #pragma unroll
        for (int i = 0; i < 2; i++) {             // 1024 chunks for B (128 rows x 8)
            int idx = tid + i * 512;
            int row = idx >> 3;
            int c8  = (idx & 7) << 3;
            cp16(&Bs[row * ASTRIDE + c8], &g_W16[(size_t)(n0 + row) * HID + kt + c8]);
        }
        asm volatile("cp.async.commit_group;\n");
    };

    load_tile(0, 0);
    load_tile(1, 1);

    for (int i = 0; i < NK; i++) {
        if (i + 2 < NK) load_tile(i + 2, (i + 2) & 3);

        if (i < NK - 2)       asm volatile("cp.async.wait_group 2;\n" ::: "memory");
        else if (i == NK - 2) asm volatile("cp.async.wait_group 1;\n" ::: "memory");
        else                  asm volatile("cp.async.wait_group 0;\n" ::: "memory");
        __syncthreads();

        const __half* As = smem + (i & 3) * STAGE;
        const __half* Bs = As + MT * ASTRIDE;

        #pragma unroll
        for (int kk = 0; kk < KT; kk += 16) {     // 4 x k16 steps
            uint32_t a[4][4], bf[4][2];
            #pragma unroll
            for (int mi = 0; mi < 4; mi++) {
                int r = wm * 64 + mi * 16;
                a[mi][0] = *(const uint32_t*)&As[(r + g    ) * ASTRIDE + kk + 2*l4    ];
                a[mi][1] = *(const uint32_t*)&As[(r + g + 8) * ASTRIDE + kk + 2*l4    ];
                a[mi][2] = *(const uint32_t*)&As[(r + g    ) * ASTRIDE + kk + 2*l4 + 8];
                a[mi][3] = *(const uint32_t*)&As[(r + g + 8) * ASTRIDE + kk + 2*l4 + 8];
            }
            #pragma unroll
            for (int ni = 0; ni < 4; ni++) {
                int c = wn * 32 + ni * 8 + g;
                bf[ni][0] = *(const uint32_t*)&Bs[c * ASTRIDE + kk + 2*l4    ];
                bf[ni][1] = *(const uint32_t*)&Bs[c * ASTRIDE + kk + 2*l4 + 8];
            }
            #pragma unroll
            for (int mi = 0; mi < 4; mi++)
                #pragma unroll
                for (int ni = 0; ni < 4; ni++)
                    asm volatile(
                        "mma.sync.aligned.m16n8k16.row.col.f32.f16.f16.f32 "
                        "{%0,%1,%2,%3}, {%4,%5,%6,%7}, {%8,%9}, {%0,%1,%2,%3};"
                        : "+f"(acc[mi][ni][0]), "+f"(acc[mi][ni][1]),
                          "+f"(acc[mi][ni][2]), "+f"(acc[mi][ni][3])
                        : "r"(a[mi][0]), "r"(a[mi][1]), "r"(a[mi][2]), "r"(a[mi][3]),
                          "r"(bf[ni][0]), "r"(bf[ni][1]));
        }
    }

    // ---- epilogue: partial sim over this block's 128 cols of tanh(z+b)*ctx ----
    float rowsum[4][2];
    #pragma unroll
    for (int mi = 0; mi < 4; mi++) { rowsum[mi][0] = 0.f; rowsum[mi][1] = 0.f; }

    #pragma unroll
    for (int ni = 0; ni < 4; ni++) {
        int col = n0 + wn * 32 + ni * 8 + 2 * l4;
        float b0 = bias[col], b1 = bias[col + 1];
        float c0 = ctx[col],  c1 = ctx[col + 1];
        #pragma unroll
        for (int mi = 0; mi < 4; mi++) {
            rowsum[mi][0] += tanhf(acc[mi][ni][0] + b0) * c0
                           + tanhf(acc[mi][ni][1] + b1) * c1;
            rowsum[mi][1] += tanhf(acc[mi][ni][2] + b0) * c0
                           + tanhf(acc[mi][ni][3] + b1) * c1;
        }
    }
    #pragma unroll
    for (int mi = 0; mi < 4; mi++)
        #pragma unroll
        for (int hf = 0; hf < 2; hf++) {
            float v = rowsum[mi][hf];
            v += __shfl_xor_sync(0xffffffffu, v, 1);
            v += __shfl_xor_sync(0xffffffffu, v, 2);
            if (l4 == 0)
                atomicAdd(&g_sim[m0 + wm * 64 + mi * 16 + g + hf * 8], v);
        }
}

// ---------------------------------------------------------------------------
// Kernel 2: softmax over seq per batch. sim index t = s*BATCH + b.
// ---------------------------------------------------------------------------
__global__ void softmax_kernel()
{
    const int b   = blockIdx.x;
    const int tid = threadIdx.x;
    __shared__ float red[256];

    float lmax = -1e30f;
    for (int s = tid; s < SEQ; s += 256)
        lmax = fmaxf(lmax, g_sim[s * BATCH + b]);
    red[tid] = lmax; __syncthreads();
    for (int o = 128; o > 0; o >>= 1) {
        if (tid < o) red[tid] = fmaxf(red[tid], red[tid + o]);
        __syncthreads();
    }
    const float m = red[0];
    __syncthreads();

    float lsum = 0.f;
    for (int s = tid; s < SEQ; s += 256) {
        float e = __expf(g_sim[s * BATCH + b] - m);
        g_probs[s * BATCH + b] = e;
        lsum += e;
    }
    red[tid] = lsum; __syncthreads();
    for (int o = 128; o > 0; o >>= 1) {
        if (tid < o) red[tid] += red[tid + o];
        __syncthreads();
    }
    const float inv = 1.f / red[0];

    for (int s = tid; s < SEQ; s += 256)
        g_probs[s * BATCH + b] *= inv;
}

// ---------------------------------------------------------------------------
// Kernel 3: attended[b,h] = sum_s x[s,b,h]*p[b,s]. float4, 64 s-chunks.
// Grid: (BATCH, 1, 64) = 2048 blocks, 128 threads. f32 X (precision).
// ---------------------------------------------------------------------------
__global__ __launch_bounds__(128)
void pool_kernel(const float* __restrict__ X, float* __restrict__ out)
{
    const int b  = blockIdx.x;
    const int h4 = threadIdx.x;
    const int s0 = blockIdx.z * (SEQ / 64);

    float4 acc = make_float4(0.f, 0.f, 0.f, 0.f);
    const float4* X4 = reinterpret_cast<const float4*>(X);

    #pragma unroll 4
    for (int s = s0; s < s0 + SEQ / 64; s++) {
        const int t = s * BATCH + b;
        const float p = g_probs[t];
        const float4 v = X4[(size_t)t * (HID / 4) + h4];
        acc.x += v.x * p; acc.y += v.y * p; acc.z += v.z * p; acc.w += v.w * p;
    }
    float* o = &out[b * HID + h4 * 4];
    atomicAdd(o + 0, acc.x);
    atomicAdd(o + 1, acc.y);
    atomicAdd(o + 2, acc.z);
    atomicAdd(o + 3, acc.w);
}

// ---------------------------------------------------------------------------
extern "C" void kernel_launch(void* const* d_in, const int* in_sizes, int n_in,
                              void* d_out, int out_size)
{
    const float* x   = (const float*)d_in[0];
    const float* W   = (const float*)d_in[1];
    const float* b   = (const float*)d_in[2];
    const float* ctx = (const float*)d_in[3];
    float* out = (float*)d_out;

    cudaFuncSetAttribute(sim_kernel,
                         cudaFuncAttributeMaxDynamicSharedMemorySize, SMEM_BYTES);

    init_kernel<<<TOK / 256, 256>>>(W, out);
    convert_kernel<<<(int)(((size_t)TOK * HID / 8) / 256), 256>>>(x);

    dim3 grid_sim(HID / NT, TOK / MT);        // n fastest -> X16 L2 reuse
    sim_kernel<<<grid_sim, 512, SMEM_BYTES>>>(b, ctx);

    softmax_kernel<<<BATCH, 256>>>();

    pool_kernel<<<dim3(BATCH, 1, 64), 128>>>(x, out);
}

// round 10
// speedup vs baseline: 2.3376x; 1.1288x over previous
#include <cuda_runtime.h>
#include <cuda_fp16.h>
#include <math.h>
#include <stdint.h>

#define SEQ   4096
#define BATCH 32
#define HID   512
#define TOK   (SEQ*BATCH)

#define MT 256
#define NT 128
#define KT 64                               // 64 halfs = 128 B per row
#define NSTAGE 4
#define ASTRIDE (KT + 8)                    // 72 halfs = 144 B (16B aligned, conflict-free)
#define STAGE   ((MT + NT) * ASTRIDE)       // halfs per stage (27648 = 55296 B)
#define SMEM_BYTES (NSTAGE * STAGE * 2)     // 221184 B

__device__ float  g_sim[TOK];                 // [batch][seq] layout
__device__ float  g_probs[TOK];               // [batch][seq] layout
__device__ __half g_X16[(size_t)TOK * HID];   // 128 MB static scratch
__device__ __half g_W16[HID * HID];

__device__ __forceinline__ uint32_t h2u(__half2 h) {
    return *reinterpret_cast<uint32_t*>(&h);
}

// ---------------------------------------------------------------------------
// Kernel 0: zero sim + output, convert W to fp16.
// ---------------------------------------------------------------------------
__global__ void init_kernel(const float* __restrict__ W, float* __restrict__ out) {
    int i = blockIdx.x * blockDim.x + threadIdx.x;   // grid covers exactly TOK
    g_sim[i] = 0.f;
    if (i < BATCH * HID) out[i] = 0.f;
    if (i < (HID * HID) / 8) {
        const float4* src = reinterpret_cast<const float4*>(W) + i * 2;
        float4 v0 = src[0], v1 = src[1];
        uint4 pk;
        pk.x = h2u(__float22half2_rn(make_float2(v0.x, v0.y)));
        pk.y = h2u(__float22half2_rn(make_float2(v0.z, v0.w)));
        pk.z = h2u(__float22half2_rn(make_float2(v1.x, v1.y)));
        pk.w = h2u(__float22half2_rn(make_float2(v1.z, v1.w)));
        reinterpret_cast<uint4*>(g_W16)[i] = pk;
    }
}

// ---------------------------------------------------------------------------
// Kernel 0b: convert X to fp16 (8 elems/thread, 16B ld/st)
// ---------------------------------------------------------------------------
__global__ __launch_bounds__(256)
void convert_kernel(const float* __restrict__ X) {
    size_t i = (size_t)blockIdx.x * blockDim.x + threadIdx.x;   // grid = TOK*HID/8
    const float4* src = reinterpret_cast<const float4*>(X) + i * 2;
    float4 v0 = src[0], v1 = src[1];
    uint4 pk;
    pk.x = h2u(__float22half2_rn(make_float2(v0.x, v0.y)));
    pk.y = h2u(__float22half2_rn(make_float2(v0.z, v0.w)));
    pk.z = h2u(__float22half2_rn(make_float2(v1.x, v1.y)));
    pk.w = h2u(__float22half2_rn(make_float2(v1.z, v1.w)));
    reinterpret_cast<uint4*>(g_X16)[i] = pk;
}

__device__ __forceinline__ void cp16(const __half* smem_dst, const __half* gsrc) {
    uint32_t s = (uint32_t)__cvta_generic_to_shared(smem_dst);
    asm volatile("cp.async.cg.shared.global [%0], [%1], 16;\n" :: "r"(s), "l"(gsrc));
}

// ---------------------------------------------------------------------------
// Kernel 1: z = X @ W^T (fp16 m16n8k16 mma, fp32 acc), fused tanh(z+b)*ctx
// -> g_sim[b][s]. Grid: (HID/NT=4, TOK/MT=512) n-fastest. 512 thr = 16 warps
// 4(m)x4(n), warp tile 64x32. 4-stage cp.async ring, depth-2, 1 sync/k-tile.
// ---------------------------------------------------------------------------
__global__ __launch_bounds__(512, 1)
void sim_kernel(const float* __restrict__ bias, const float* __restrict__ ctx)
{
    extern __shared__ __half smem[];

    const int tid  = threadIdx.x;
    const int n0   = blockIdx.x * NT;
    const int m0   = blockIdx.y * MT;
    const int warp = tid >> 5;
    const int lane = tid & 31;
    const int g    = lane >> 2;
    const int l4   = lane & 3;
    const int wm   = warp & 3;        // 0..3 -> 64 rows each
    const int wn   = warp >> 2;       // 0..3 -> 32 cols each

    float acc[4][4][4];
    #pragma unroll
    for (int i = 0; i < 4; i++)
        #pragma unroll
        for (int j = 0; j < 4; j++)
            #pragma unroll
            for (int c = 0; c < 4; c++) acc[i][j][c] = 0.f;

    const int NK = HID / KT;   // 8 k-tiles

    auto load_tile = [&](int kt_idx, int s) {
        __half* As = smem + s * STAGE;
        __half* Bs = As + MT * ASTRIDE;
        const int kt = kt_idx * KT;
        #pragma unroll
        for (int i = 0; i < 4; i++) {             // 2048 chunks for A (256 rows x 8)
            int idx = tid + i * 512;
            int row = idx >> 3;
            int c8  = (idx & 7) << 3;
            cp16(&As[row * ASTRIDE + c8], &g_X16[(size_t)(m0 + row) * HID + kt + c8]);
        }
        #pragma unroll
        for (int i = 0; i < 2; i++) {             // 1024 chunks for B (128 rows x 8)
            int idx = tid + i * 512;
            int row = idx >> 3;
            int c8  = (idx & 7) << 3;
            cp16(&Bs[row * ASTRIDE + c8], &g_W16[(size_t)(n0 + row) * HID + kt + c8]);
        }
        asm volatile("cp.async.commit_group;\n");
    };

    load_tile(0, 0);
    load_tile(1, 1);

    for (int i = 0; i < NK; i++) {
        if (i + 2 < NK) load_tile(i + 2, (i + 2) & 3);

        if (i < NK - 2)       asm volatile("cp.async.wait_group 2;\n" ::: "memory");
        else if (i == NK - 2) asm volatile("cp.async.wait_group 1;\n" ::: "memory");
        else                  asm volatile("cp.async.wait_group 0;\n" ::: "memory");
        __syncthreads();

        const __half* As = smem + (i & 3) * STAGE;
        const __half* Bs = As + MT * ASTRIDE;

        #pragma unroll
        for (int kk = 0; kk < KT; kk += 16) {
            uint32_t a[4][4], bf[4][2];
            #pragma unroll
            for (int mi = 0; mi < 4; mi++) {
                int r = wm * 64 + mi * 16;
                a[mi][0] = *(const uint32_t*)&As[(r + g    ) * ASTRIDE + kk + 2*l4    ];
                a[mi][1] = *(const uint32_t*)&As[(r + g + 8) * ASTRIDE + kk + 2*l4    ];
                a[mi][2] = *(const uint32_t*)&As[(r + g    ) * ASTRIDE + kk + 2*l4 + 8];
                a[mi][3] = *(const uint32_t*)&As[(r + g + 8) * ASTRIDE + kk + 2*l4 + 8];
            }
            #pragma unroll
            for (int ni = 0; ni < 4; ni++) {
                int c = wn * 32 + ni * 8 + g;
                bf[ni][0] = *(const uint32_t*)&Bs[c * ASTRIDE + kk + 2*l4    ];
                bf[ni][1] = *(const uint32_t*)&Bs[c * ASTRIDE + kk + 2*l4 + 8];
            }
            #pragma unroll
            for (int mi = 0; mi < 4; mi++)
                #pragma unroll
                for (int ni = 0; ni < 4; ni++)
                    asm volatile(
                        "mma.sync.aligned.m16n8k16.row.col.f32.f16.f16.f32 "
                        "{%0,%1,%2,%3}, {%4,%5,%6,%7}, {%8,%9}, {%0,%1,%2,%3};"
                        : "+f"(acc[mi][ni][0]), "+f"(acc[mi][ni][1]),
                          "+f"(acc[mi][ni][2]), "+f"(acc[mi][ni][3])
                        : "r"(a[mi][0]), "r"(a[mi][1]), "r"(a[mi][2]), "r"(a[mi][3]),
                          "r"(bf[ni][0]), "r"(bf[ni][1]));
        }
    }

    // ---- epilogue: partial sim over this block's 128 cols of tanh(z+b)*ctx ----
    float rowsum[4][2];
    #pragma unroll
    for (int mi = 0; mi < 4; mi++) { rowsum[mi][0] = 0.f; rowsum[mi][1] = 0.f; }

    #pragma unroll
    for (int ni = 0; ni < 4; ni++) {
        int col = n0 + wn * 32 + ni * 8 + 2 * l4;
        float b0 = bias[col], b1 = bias[col + 1];
        float c0 = ctx[col],  c1 = ctx[col + 1];
        #pragma unroll
        for (int mi = 0; mi < 4; mi++) {
            rowsum[mi][0] += tanhf(acc[mi][ni][0] + b0) * c0
                           + tanhf(acc[mi][ni][1] + b1) * c1;
            rowsum[mi][1] += tanhf(acc[mi][ni][2] + b0) * c0
                           + tanhf(acc[mi][ni][3] + b1) * c1;
        }
    }
    #pragma unroll
    for (int mi = 0; mi < 4; mi++)
        #pragma unroll
        for (int hf = 0; hf < 2; hf++) {
            float v = rowsum[mi][hf];
            v += __shfl_xor_sync(0xffffffffu, v, 1);
            v += __shfl_xor_sync(0xffffffffu, v, 2);
            if (l4 == 0) {
                const int m = m0 + wm * 64 + mi * 16 + g + hf * 8;   // token id
                // transposed: sim[b][s] with b = m & 31, s = m >> 5
                atomicAdd(&g_sim[(m & 31) * SEQ + (m >> 5)], v);
            }
        }
}

// ---------------------------------------------------------------------------
// Kernel 2: softmax over seq per batch, [batch][seq] layout, fully coalesced.
// 32 blocks x 1024 threads; each thread owns one float4 (whole row resident).
// ---------------------------------------------------------------------------
__global__ __launch_bounds__(1024)
void softmax_kernel()
{
    const int b   = blockIdx.x;
    const int tid = threadIdx.x;
    const int lane = tid & 31;
    const int wid  = tid >> 5;
    __shared__ float red[32];

    float4 v = reinterpret_cast<const float4*>(g_sim + b * SEQ)[tid];

    // block max
    float m = fmaxf(fmaxf(v.x, v.y), fmaxf(v.z, v.w));
    #pragma unroll
    for (int o = 16; o > 0; o >>= 1)
        m = fmaxf(m, __shfl_xor_sync(0xffffffffu, m, o));
    if (lane == 0) red[wid] = m;
    __syncthreads();
    if (wid == 0) {
        float t = red[lane];
        #pragma unroll
        for (int o = 16; o > 0; o >>= 1)
            t = fmaxf(t, __shfl_xor_sync(0xffffffffu, t, o));
        red[lane] = t;                    // all 32 slots = block max
    }
    __syncthreads();
    m = red[0];

    // exp + block sum
    float4 e;
    e.x = __expf(v.x - m); e.y = __expf(v.y - m);
    e.z = __expf(v.z - m); e.w = __expf(v.w - m);
    float s = e.x + e.y + e.z + e.w;
    #pragma unroll
    for (int o = 16; o > 0; o >>= 1)
        s += __shfl_xor_sync(0xffffffffu, s, o);
    __syncthreads();                      // before red reuse
    if (lane == 0) red[wid] = s;
    __syncthreads();
    if (wid == 0) {
        float t = red[lane];
        #pragma unroll
        for (int o = 16; o > 0; o >>= 1)
            t += __shfl_xor_sync(0xffffffffu, t, o);
        red[lane] = t;
    }
    __syncthreads();
    const float inv = 1.f / red[0];

    e.x *= inv; e.y *= inv; e.z *= inv; e.w *= inv;
    reinterpret_cast<float4*>(g_probs + b * SEQ)[tid] = e;
}

// ---------------------------------------------------------------------------
// Kernel 3: attended[b,h] = sum_s x16[s,b,h]*p[b,s]. fp16 X, fp32 acc.
// Grid: (BATCH, 1, 64) = 2048 blocks, 128 threads (4 halfs each = 512).
// ---------------------------------------------------------------------------
__global__ __launch_bounds__(128)
void pool_kernel(float* __restrict__ out)
{
    const int b  = blockIdx.x;
    const int h4 = threadIdx.x;               // owns halfs [4*h4, 4*h4+4)
    const int s0 = blockIdx.z * (SEQ / 64);

    float acc0 = 0.f, acc1 = 0.f, acc2 = 0.f, acc3 = 0.f;
    const uint2* X2 = reinterpret_cast<const uint2*>(g_X16);

    #pragma unroll 4
    for (int s = s0; s < s0 + SEQ / 64; s++) {
        const size_t t = (size_t)s * BATCH + b;
        const float p = g_probs[b * SEQ + s];
        const uint2 u = X2[t * (HID / 4) + h4];
        const float2 lo = __half22float2(*reinterpret_cast<const __half2*>(&u.x));
        const float2 hi = __half22float2(*reinterpret_cast<const __half2*>(&u.y));
        acc0 += lo.x * p; acc1 += lo.y * p; acc2 += hi.x * p; acc3 += hi.y * p;
    }
    float* o = &out[b * HID + h4 * 4];
    atomicAdd(o + 0, acc0);
    atomicAdd(o + 1, acc1);
    atomicAdd(o + 2, acc2);
    atomicAdd(o + 3, acc3);
}

// ---------------------------------------------------------------------------
extern "C" void kernel_launch(void* const* d_in, const int* in_sizes, int n_in,
                              void* d_out, int out_size)
{
    const float* x   = (const float*)d_in[0];
    const float* W   = (const float*)d_in[1];
    const float* b   = (const float*)d_in[2];
    const float* ctx = (const float*)d_in[3];
    float* out = (float*)d_out;

    cudaFuncSetAttribute(sim_kernel,
                         cudaFuncAttributeMaxDynamicSharedMemorySize, SMEM_BYTES);

    init_kernel<<<TOK / 256, 256>>>(W, out);
    convert_kernel<<<(int)(((size_t)TOK * HID / 8) / 256), 256>>>(x);

    dim3 grid_sim(HID / NT, TOK / MT);        // n fastest -> X16 L2 reuse
    sim_kernel<<<grid_sim, 512, SMEM_BYTES>>>(b, ctx);

    softmax_kernel<<<BATCH, 1024>>>();

    pool_kernel<<<dim3(BATCH, 1, 64), 128>>>(out);
}

// round 11
// speedup vs baseline: 2.7852x; 1.1915x over previous
#include <cuda_runtime.h>
#include <cuda_fp16.h>
#include <math.h>
#include <stdint.h>

#define SEQ   4096
#define BATCH 32
#define HID   512
#define TOK   (SEQ*BATCH)

#define MT 256
#define NT 128
#define KT 64                               // 64 halfs = 128 B per row
#define NSTAGE 4
#define ASTRIDE (KT + 8)                    // 72 halfs = 144 B (conflict-free for LDSM)
#define STAGE   ((MT + NT) * ASTRIDE)       // halfs per stage (27648 = 55296 B)
#define SMEM_BYTES (NSTAGE * STAGE * 2)     // 221184 B

__device__ float  g_sim[TOK];                 // [batch][seq] layout
__device__ float  g_probs[TOK];               // [batch][seq] layout
__device__ __half g_X16[(size_t)TOK * HID];   // 128 MB static scratch
__device__ __half g_W16[HID * HID];

__device__ __forceinline__ uint32_t h2u(__half2 h) {
    return *reinterpret_cast<uint32_t*>(&h);
}
__device__ __forceinline__ float tanh_fast(float x) {
    float y;
    asm("tanh.approx.f32 %0, %1;" : "=f"(y) : "f"(x));
    return y;
}

// ---------------------------------------------------------------------------
// Kernel 0: convert X to fp16 + zero sim/out + convert W (merged init).
// Grid covers TOK*HID/8 threads.
// ---------------------------------------------------------------------------
__global__ __launch_bounds__(256)
void convert_kernel(const float* __restrict__ X, const float* __restrict__ W,
                    float* __restrict__ out) {
    size_t i = (size_t)blockIdx.x * blockDim.x + threadIdx.x;
    const float4* src = reinterpret_cast<const float4*>(X) + i * 2;
    float4 v0 = src[0], v1 = src[1];
    uint4 pk;
    pk.x = h2u(__float22half2_rn(make_float2(v0.x, v0.y)));
    pk.y = h2u(__float22half2_rn(make_float2(v0.z, v0.w)));
    pk.z = h2u(__float22half2_rn(make_float2(v1.x, v1.y)));
    pk.w = h2u(__float22half2_rn(make_float2(v1.z, v1.w)));
    reinterpret_cast<uint4*>(g_X16)[i] = pk;

    if (i < TOK) g_sim[i] = 0.f;
    if (i < BATCH * HID) out[i] = 0.f;
    if (i < (HID * HID) / 8) {
        const float4* ws = reinterpret_cast<const float4*>(W) + i * 2;
        float4 w0 = ws[0], w1 = ws[1];
        uint4 wp;
        wp.x = h2u(__float22half2_rn(make_float2(w0.x, w0.y)));
        wp.y = h2u(__float22half2_rn(make_float2(w0.z, w0.w)));
        wp.z = h2u(__float22half2_rn(make_float2(w1.x, w1.y)));
        wp.w = h2u(__float22half2_rn(make_float2(w1.z, w1.w)));
        reinterpret_cast<uint4*>(g_W16)[i] = wp;
    }
}

__device__ __forceinline__ void cp16(const __half* smem_dst, const __half* gsrc) {
    uint32_t s = (uint32_t)__cvta_generic_to_shared(smem_dst);
    asm volatile("cp.async.cg.shared.global [%0], [%1], 16;\n" :: "r"(s), "l"(gsrc));
}

// ---------------------------------------------------------------------------
// Kernel 1: z = X @ W^T (fp16 m16n8k16 mma via ldmatrix, fp32 acc), fused
// tanh(z+b)*ctx -> g_sim[b][s]. Grid: (HID/NT=4, TOK/MT=512) n-fastest.
// 512 thr = 16 warps 4(m)x4(n), warp tile 64x32. 4-stage cp.async ring.
// ---------------------------------------------------------------------------
__global__ __launch_bounds__(512, 1)
void sim_kernel(const float* __restrict__ bias, const float* __restrict__ ctx)
{
    extern __shared__ __half smem[];
    const uint32_t smem_s = (uint32_t)__cvta_generic_to_shared(smem);

    const int tid  = threadIdx.x;
    const int n0   = blockIdx.x * NT;
    const int m0   = blockIdx.y * MT;
    const int warp = tid >> 5;
    const int lane = tid & 31;
    const int g    = lane >> 2;
    const int l4   = lane & 3;
    const int wm   = warp & 3;        // 0..3 -> 64 rows each
    const int wn   = warp >> 2;       // 0..3 -> 32 cols each

    // ldmatrix per-lane address offsets (bytes), relative to stage base
    const uint32_t a_lane_off =
        (uint32_t)(((wm * 64 + (lane & 15)) * ASTRIDE + ((lane >> 4) << 3)) * 2);
    const uint32_t b_lane_off =
        (uint32_t)((MT * ASTRIDE
                   + (wn * 32 + ((lane >> 4) << 3) + (lane & 7)) * ASTRIDE
                   + (((lane >> 3) & 1) << 3)) * 2);

    float acc[4][4][4];
    #pragma unroll
    for (int i = 0; i < 4; i++)
        #pragma unroll
        for (int j = 0; j < 4; j++)
            #pragma unroll
            for (int c = 0; c < 4; c++) acc[i][j][c] = 0.f;

    const int NK = HID / KT;   // 8 k-tiles

    auto load_tile = [&](int kt_idx, int s) {
        __half* As = smem + s * STAGE;
        __half* Bs = As + MT * ASTRIDE;
        const int kt = kt_idx * KT;
        #pragma unroll
        for (int i = 0; i < 4; i++) {             // 2048 chunks for A (256 rows x 8)
            int idx = tid + i * 512;
            int row = idx >> 3;
            int c8  = (idx & 7) << 3;
            cp16(&As[row * ASTRIDE + c8], &g_X16[(size_t)(m0 + row) * HID + kt + c8]);
        }
        #pragma unroll
        for (int i = 0; i < 2; i++) {             // 1024 chunks for B (128 rows x 8)
            int idx = tid + i * 512;
            int row = idx >> 3;
            int c8  = (idx & 7) << 3;
            cp16(&Bs[row * ASTRIDE + c8], &g_W16[(size_t)(n0 + row) * HID + kt + c8]);
        }
        asm volatile("cp.async.commit_group;\n");
    };

    load_tile(0, 0);
    load_tile(1, 1);

    for (int i = 0; i < NK; i++) {
        if (i + 2 < NK) load_tile(i + 2, (i + 2) & 3);

        if (i < NK - 2)       asm volatile("cp.async.wait_group 2;\n" ::: "memory");
        else if (i == NK - 2) asm volatile("cp.async.wait_group 1;\n" ::: "memory");
        else                  asm volatile("cp.async.wait_group 0;\n" ::: "memory");
        __syncthreads();

        const uint32_t stage_s = smem_s + (uint32_t)((i & 3) * STAGE * 2);
        const uint32_t a_base  = stage_s + a_lane_off;
        const uint32_t b_base  = stage_s + b_lane_off;

        #pragma unroll
        for (int kk = 0; kk < KT; kk += 16) {
            uint32_t a[4][4], bf[4][2];
            #pragma unroll
            for (int mi = 0; mi < 4; mi++) {
                uint32_t addr = a_base + (uint32_t)((mi * 16 * ASTRIDE + kk) * 2);
                asm volatile(
                    "ldmatrix.sync.aligned.m8n8.x4.shared.b16 {%0,%1,%2,%3}, [%4];"
                    : "=r"(a[mi][0]), "=r"(a[mi][1]), "=r"(a[mi][2]), "=r"(a[mi][3])
                    : "r"(addr));
            }
            #pragma unroll
            for (int np = 0; np < 2; np++) {
                uint32_t addr = b_base + (uint32_t)((np * 16 * ASTRIDE + kk) * 2);
                asm volatile(
                    "ldmatrix.sync.aligned.m8n8.x4.shared.b16 {%0,%1,%2,%3}, [%4];"
                    : "=r"(bf[2*np][0]), "=r"(bf[2*np][1]),
                      "=r"(bf[2*np+1][0]), "=r"(bf[2*np+1][1])
                    : "r"(addr));
            }
            #pragma unroll
            for (int mi = 0; mi < 4; mi++)
                #pragma unroll
                for (int ni = 0; ni < 4; ni++)
                    asm volatile(
                        "mma.sync.aligned.m16n8k16.row.col.f32.f16.f16.f32 "
                        "{%0,%1,%2,%3}, {%4,%5,%6,%7}, {%8,%9}, {%0,%1,%2,%3};"
                        : "+f"(acc[mi][ni][0]), "+f"(acc[mi][ni][1]),
                          "+f"(acc[mi][ni][2]), "+f"(acc[mi][ni][3])
                        : "r"(a[mi][0]), "r"(a[mi][1]), "r"(a[mi][2]), "r"(a[mi][3]),
                          "r"(bf[ni][0]), "r"(bf[ni][1]));
        }
    }

    // ---- epilogue: partial sim over this block's 128 cols of tanh(z+b)*ctx ----
    float rowsum[4][2];
    #pragma unroll
    for (int mi = 0; mi < 4; mi++) { rowsum[mi][0] = 0.f; rowsum[mi][1] = 0.f; }

    #pragma unroll
    for (int ni = 0; ni < 4; ni++) {
        int col = n0 + wn * 32 + ni * 8 + 2 * l4;
        float b0 = bias[col], b1 = bias[col + 1];
        float c0 = ctx[col],  c1 = ctx[col + 1];
        #pragma unroll
        for (int mi = 0; mi < 4; mi++) {
            rowsum[mi][0] += tanh_fast(acc[mi][ni][0] + b0) * c0
                           + tanh_fast(acc[mi][ni][1] + b1) * c1;
            rowsum[mi][1] += tanh_fast(acc[mi][ni][2] + b0) * c0
                           + tanh_fast(acc[mi][ni][3] + b1) * c1;
        }
    }
    #pragma unroll
    for (int mi = 0; mi < 4; mi++)
        #pragma unroll
        for (int hf = 0; hf < 2; hf++) {
            float v = rowsum[mi][hf];
            v += __shfl_xor_sync(0xffffffffu, v, 1);
            v += __shfl_xor_sync(0xffffffffu, v, 2);
            if (l4 == 0) {
                const int m = m0 + wm * 64 + mi * 16 + g + hf * 8;   // token id
                atomicAdd(&g_sim[(m & 31) * SEQ + (m >> 5)], v);     // sim[b][s]
            }
        }
}

// ---------------------------------------------------------------------------
// Kernel 2: softmax over seq per batch, [batch][seq], whole row in registers.
// ---------------------------------------------------------------------------
__global__ __launch_bounds__(1024)
void softmax_kernel()
{
    const int b   = blockIdx.x;
    const int tid = threadIdx.x;
    const int lane = tid & 31;
    const int wid  = tid >> 5;
    __shared__ float red[32];

    float4 v = reinterpret_cast<const float4*>(g_sim + b * SEQ)[tid];

    float m = fmaxf(fmaxf(v.x, v.y), fmaxf(v.z, v.w));
    #pragma unroll
    for (int o = 16; o > 0; o >>= 1)
        m = fmaxf(m, __shfl_xor_sync(0xffffffffu, m, o));
    if (lane == 0) red[wid] = m;
    __syncthreads();
    if (wid == 0) {
        float t = red[lane];
        #pragma unroll
        for (int o = 16; o > 0; o >>= 1)
            t = fmaxf(t, __shfl_xor_sync(0xffffffffu, t, o));
        red[lane] = t;
    }
    __syncthreads();
    m = red[0];

    float4 e;
    e.x = __expf(v.x - m); e.y = __expf(v.y - m);
    e.z = __expf(v.z - m); e.w = __expf(v.w - m);
    float s = e.x + e.y + e.z + e.w;
    #pragma unroll
    for (int o = 16; o > 0; o >>= 1)
        s += __shfl_xor_sync(0xffffffffu, s, o);
    __syncthreads();
    if (lane == 0) red[wid] = s;
    __syncthreads();
    if (wid == 0) {
        float t = red[lane];
        #pragma unroll
        for (int o = 16; o > 0; o >>= 1)
            t += __shfl_xor_sync(0xffffffffu, t, o);
        red[lane] = t;
    }
    __syncthreads();
    const float inv = 1.f / red[0];

    e.x *= inv; e.y *= inv; e.z *= inv; e.w *= inv;
    reinterpret_cast<float4*>(g_probs + b * SEQ)[tid] = e;
}

// ---------------------------------------------------------------------------
// Kernel 3: attended[b,h] = sum_s x16[s,b,h]*p[b,s]. fp16 X, fp32 acc.
// Grid: (BATCH, 1, 64), 128 threads, s-unroll 8.
// ---------------------------------------------------------------------------
__global__ __launch_bounds__(128)
void pool_kernel(float* __restrict__ out)
{
    const int b  = blockIdx.x;
    const int h4 = threadIdx.x;
    const int s0 = blockIdx.z * (SEQ / 64);

    float acc0 = 0.f, acc1 = 0.f, acc2 = 0.f, acc3 = 0.f;
    const uint2* X2 = reinterpret_cast<const uint2*>(g_X16);

    #pragma unroll 8
    for (int s = s0; s < s0 + SEQ / 64; s++) {
        const size_t t = (size_t)s * BATCH + b;
        const float p = g_probs[b * SEQ + s];
        const uint2 u = X2[t * (HID / 4) + h4];
        const float2 lo = __half22float2(*reinterpret_cast<const __half2*>(&u.x));
        const float2 hi = __half22float2(*reinterpret_cast<const __half2*>(&u.y));
        acc0 += lo.x * p; acc1 += lo.y * p; acc2 += hi.x * p; acc3 += hi.y * p;
    }
    float* o = &out[b * HID + h4 * 4];
    atomicAdd(o + 0, acc0);
    atomicAdd(o + 1, acc1);
    atomicAdd(o + 2, acc2);
    atomicAdd(o + 3, acc3);
}

// ---------------------------------------------------------------------------
extern "C" void kernel_launch(void* const* d_in, const int* in_sizes, int n_in,
                              void* d_out, int out_size)
{
    const float* x   = (const float*)d_in[0];
    const float* W   = (const float*)d_in[1];
    const float* b   = (const float*)d_in[2];
    const float* ctx = (const float*)d_in[3];
    float* out = (float*)d_out;

    cudaFuncSetAttribute(sim_kernel,
                         cudaFuncAttributeMaxDynamicSharedMemorySize, SMEM_BYTES);

    convert_kernel<<<(int)(((size_t)TOK * HID / 8) / 256), 256>>>(x, W, out);

    dim3 grid_sim(HID / NT, TOK / MT);        // n fastest -> X16 L2 reuse
    sim_kernel<<<grid_sim, 512, SMEM_BYTES>>>(b, ctx);

    softmax_kernel<<<BATCH, 1024>>>();

    pool_kernel<<<dim3(BATCH, 1, 64), 128>>>(out);
}